// round 1
// baseline (speedup 1.0000x reference)
#include <cuda_runtime.h>
#include <math.h>

#define L_SEQ 2048
#define B_SZ 2
#define E_DIM 256
#define NH 8
#define HD 32
#define M_ROWS (L_SEQ * B_SZ)   // 4096 rows, row index = l*B + b

// Scratch (allocation-free rule: __device__ globals)
static __device__ float g_Q[M_ROWS * E_DIM];
static __device__ float g_K[M_ROWS * E_DIM];
static __device__ float g_V[M_ROWS * E_DIM];
static __device__ float g_O[M_ROWS * E_DIM];

// ---------------------------------------------------------------------------
// GEMM: out[M,N] = X[M,256] @ W[256,N] + bias[N], M=4096, N=256, K=256
// Tile 64x64, BK=16, 256 threads, 4x4 register tile per thread.
// ---------------------------------------------------------------------------
__global__ __launch_bounds__(256) void gemm_bias_kernel(
    const float* __restrict__ X, const float* __restrict__ W,
    const float* __restrict__ bias, float* __restrict__ out)
{
    __shared__ float As[16][68];   // As[k][m]  (A transposed in smem)
    __shared__ float Bs[16][68];   // Bs[k][n]

    const int tid = threadIdx.x;
    const int tx  = tid & 15;      // 0..15 -> n groups of 4
    const int ty  = tid >> 4;      // 0..15 -> m groups of 4
    const int mBase = blockIdx.y * 64;
    const int nBase = blockIdx.x * 64;

    // load indexing
    const int lr = tid >> 2;            // 0..63 : A row
    const int lk = (tid & 3) << 2;      // 0,4,8,12 : A k-offset
    const int wr = tid >> 4;            // 0..15 : B k-row
    const int wn = (tid & 15) << 2;     // 0..60 : B n-offset

    float c[4][4] = {};

    for (int k0 = 0; k0 < 256; k0 += 16) {
        float4 a = *(const float4*)&X[(mBase + lr) * 256 + k0 + lk];
        As[lk + 0][lr] = a.x; As[lk + 1][lr] = a.y;
        As[lk + 2][lr] = a.z; As[lk + 3][lr] = a.w;
        float4 bvec = *(const float4*)&W[(k0 + wr) * 256 + nBase + wn];
        *(float4*)&Bs[wr][wn] = bvec;
        __syncthreads();

        #pragma unroll
        for (int k = 0; k < 16; k++) {
            float4 av = *(float4*)&As[k][ty * 4];
            float4 bv = *(float4*)&Bs[k][tx * 4];
            float ar[4] = {av.x, av.y, av.z, av.w};
            float br[4] = {bv.x, bv.y, bv.z, bv.w};
            #pragma unroll
            for (int i = 0; i < 4; i++)
                #pragma unroll
                for (int j = 0; j < 4; j++)
                    c[i][j] += ar[i] * br[j];
        }
        __syncthreads();
    }

    float4 bb = *(const float4*)&bias[nBase + tx * 4];
    float bl[4] = {bb.x, bb.y, bb.z, bb.w};
    #pragma unroll
    for (int i = 0; i < 4; i++) {
        float4 o;
        o.x = c[i][0] + bl[0];
        o.y = c[i][1] + bl[1];
        o.z = c[i][2] + bl[2];
        o.w = c[i][3] + bl[3];
        *(float4*)&out[(mBase + ty * 4 + i) * 256 + nBase + tx * 4] = o;
    }
}

// ---------------------------------------------------------------------------
// Flash attention, fp32. Grid: (L/64, B*NH). 256 threads.
// BQ=64 queries per CTA, iterate key tiles of 64, D=32.
// Thread (ty,tx) owns S rows 4ty..4ty+3 x cols 4tx..4tx+3, and O rows
// 4ty..4ty+3 x dims {2tx, 2tx+1}. Softmax stats reduced over the 16 tx
// lanes with shfl (xor<=8 stays within the ty half-warp).
// ---------------------------------------------------------------------------
__global__ __launch_bounds__(256) void attn_kernel()
{
    __shared__ float Qs[32][68];   // Qs[d][q]  (pre-scaled by 1/sqrt(D))
    __shared__ float Ks[32][68];   // Ks[d][k]
    __shared__ float Vs[64][36];   // Vs[k][d]
    __shared__ float Ps[64][68];   // Ps[q][k]

    const int tid = threadIdx.x;
    const int tx  = tid & 15;
    const int ty  = tid >> 4;
    const int bh  = blockIdx.y;          // 0..15
    const int b   = bh / NH;
    const int h   = bh % NH;
    const int qBase = blockIdx.x * 64;
    const float scale = 0.17677669529663687f;   // 32^-0.5

    // load Q tile (transposed, pre-scaled)
    for (int idx = tid; idx < 64 * 8; idx += 256) {
        int q  = idx >> 3;
        int dg = (idx & 7) << 2;
        const float4 v = *(const float4*)&g_Q[((qBase + q) * B_SZ + b) * E_DIM + h * HD + dg];
        Qs[dg + 0][q] = v.x * scale;
        Qs[dg + 1][q] = v.y * scale;
        Qs[dg + 2][q] = v.z * scale;
        Qs[dg + 3][q] = v.w * scale;
    }

    float m_run[4], l_run[4], o[4][2];
    #pragma unroll
    for (int i = 0; i < 4; i++) {
        m_run[i] = -1e30f; l_run[i] = 0.f; o[i][0] = 0.f; o[i][1] = 0.f;
    }
    __syncthreads();

    for (int kt = 0; kt < L_SEQ / 64; kt++) {
        // load K (transposed) and V tiles
        for (int idx = tid; idx < 64 * 8; idx += 256) {
            int kk = idx >> 3;
            int dg = (idx & 7) << 2;
            int grow = ((kt * 64 + kk) * B_SZ + b) * E_DIM + h * HD + dg;
            float4 v = *(const float4*)&g_K[grow];
            Ks[dg + 0][kk] = v.x; Ks[dg + 1][kk] = v.y;
            Ks[dg + 2][kk] = v.z; Ks[dg + 3][kk] = v.w;
            float4 w = *(const float4*)&g_V[grow];
            *(float4*)&Vs[kk][dg] = w;
        }
        __syncthreads();

        // S = Q K^T (scaled)
        float s[4][4] = {};
        #pragma unroll 8
        for (int d = 0; d < 32; d++) {
            float4 qv = *(float4*)&Qs[d][ty * 4];
            float4 kv = *(float4*)&Ks[d][tx * 4];
            float qa[4] = {qv.x, qv.y, qv.z, qv.w};
            float ka[4] = {kv.x, kv.y, kv.z, kv.w};
            #pragma unroll
            for (int i = 0; i < 4; i++)
                #pragma unroll
                for (int j = 0; j < 4; j++)
                    s[i][j] += qa[i] * ka[j];
        }

        // online softmax update, write P tile
        #pragma unroll
        for (int i = 0; i < 4; i++) {
            float mx = fmaxf(fmaxf(s[i][0], s[i][1]), fmaxf(s[i][2], s[i][3]));
            #pragma unroll
            for (int off = 1; off < 16; off <<= 1)
                mx = fmaxf(mx, __shfl_xor_sync(0xffffffffu, mx, off));
            float mnew  = fmaxf(m_run[i], mx);
            float alpha = __expf(m_run[i] - mnew);
            float rs = 0.f;
            #pragma unroll
            for (int j = 0; j < 4; j++) {
                s[i][j] = __expf(s[i][j] - mnew);
                rs += s[i][j];
            }
            #pragma unroll
            for (int off = 1; off < 16; off <<= 1)
                rs += __shfl_xor_sync(0xffffffffu, rs, off);
            l_run[i] = l_run[i] * alpha + rs;
            m_run[i] = mnew;
            o[i][0] *= alpha;
            o[i][1] *= alpha;
            *(float4*)&Ps[ty * 4 + i][tx * 4] =
                make_float4(s[i][0], s[i][1], s[i][2], s[i][3]);
        }
        __syncthreads();

        // O += P @ V
        #pragma unroll 4
        for (int k = 0; k < 64; k += 4) {
            float2 v0 = *(float2*)&Vs[k + 0][tx * 2];
            float2 v1 = *(float2*)&Vs[k + 1][tx * 2];
            float2 v2 = *(float2*)&Vs[k + 2][tx * 2];
            float2 v3 = *(float2*)&Vs[k + 3][tx * 2];
            #pragma unroll
            for (int i = 0; i < 4; i++) {
                float4 p = *(float4*)&Ps[ty * 4 + i][k];
                o[i][0] += p.x * v0.x + p.y * v1.x + p.z * v2.x + p.w * v3.x;
                o[i][1] += p.x * v0.y + p.y * v1.y + p.z * v2.y + p.w * v3.y;
            }
        }
        __syncthreads();
    }

    // epilogue: normalize and store
    #pragma unroll
    for (int i = 0; i < 4; i++) {
        float inv = 1.f / l_run[i];
        int l = qBase + ty * 4 + i;
        float2 res;
        res.x = o[i][0] * inv;
        res.y = o[i][1] * inv;
        *(float2*)&g_O[(l * B_SZ + b) * E_DIM + h * HD + tx * 2] = res;
    }
}

// ---------------------------------------------------------------------------
extern "C" void kernel_launch(void* const* d_in, const int* in_sizes, int n_in,
                              void* d_out, int out_size)
{
    const float* query = (const float*)d_in[0];
    const float* key_  = (const float*)d_in[1];
    const float* value = (const float*)d_in[2];
    const float* Wq = (const float*)d_in[3];
    const float* bq = (const float*)d_in[4];
    const float* Wk = (const float*)d_in[5];
    const float* bk = (const float*)d_in[6];
    const float* Wv = (const float*)d_in[7];
    const float* bv = (const float*)d_in[8];
    const float* Wp = (const float*)d_in[9];
    const float* bp = (const float*)d_in[10];
    float* out = (float*)d_out;

    float *qbuf, *kbuf, *vbuf, *obuf;
    cudaGetSymbolAddress((void**)&qbuf, g_Q);
    cudaGetSymbolAddress((void**)&kbuf, g_K);
    cudaGetSymbolAddress((void**)&vbuf, g_V);
    cudaGetSymbolAddress((void**)&obuf, g_O);

    dim3 gg(E_DIM / 64, M_ROWS / 64);   // (4, 64)
    gemm_bias_kernel<<<gg, 256>>>(query, Wq, bq, qbuf);
    gemm_bias_kernel<<<gg, 256>>>(key_,  Wk, bk, kbuf);
    gemm_bias_kernel<<<gg, 256>>>(value, Wv, bv, vbuf);
    attn_kernel<<<dim3(L_SEQ / 64, B_SZ * NH), 256>>>();
    gemm_bias_kernel<<<gg, 256>>>(obuf, Wp, bp, out);
}

// round 2
// speedup vs baseline: 1.2272x; 1.2272x over previous
#include <cuda_runtime.h>
#include <math.h>
#include <stdint.h>

#define L_SEQ 2048
#define B_SZ 2
#define E_DIM 256
#define NH 8
#define HD 32
#define M_ROWS (L_SEQ * B_SZ)   // 4096

// Scratch (allocation-free rule: __device__ globals)
static __device__ float g_Q[M_ROWS * E_DIM];
static __device__ float g_K[M_ROWS * E_DIM];
static __device__ float g_V[M_ROWS * E_DIM];
static __device__ float g_O[M_ROWS * E_DIM];

// ---------------------------------------------------------------------------
// helpers: tf32 convert / hi-lo split / mma
// ---------------------------------------------------------------------------
__device__ __forceinline__ uint32_t f2tf(float x) {
    uint32_t r; asm("cvt.rna.tf32.f32 %0, %1;" : "=r"(r) : "f"(x)); return r;
}
__device__ __forceinline__ void split2(float x, float& hi, float& lo) {
    uint32_t h = f2tf(x);
    hi = __uint_as_float(h);
    lo = __uint_as_float(f2tf(x - hi));
}
__device__ __forceinline__ void mma8(float c[4], const uint32_t a[4],
                                     uint32_t b0, uint32_t b1) {
    asm volatile(
        "mma.sync.aligned.m16n8k8.row.col.f32.tf32.tf32.f32 "
        "{%0,%1,%2,%3}, {%4,%5,%6,%7}, {%8,%9}, {%0,%1,%2,%3};"
        : "+f"(c[0]), "+f"(c[1]), "+f"(c[2]), "+f"(c[3])
        : "r"(a[0]), "r"(a[1]), "r"(a[2]), "r"(a[3]), "r"(b0), "r"(b1));
}

// ---------------------------------------------------------------------------
// GEMM: out[M,N] = X[M,256] @ W[256,N] + bias[N]  (fp32 SIMT, unchanged)
// ---------------------------------------------------------------------------
__global__ __launch_bounds__(256) void gemm_bias_kernel(
    const float* __restrict__ X, const float* __restrict__ W,
    const float* __restrict__ bias, float* __restrict__ out)
{
    __shared__ float As[16][68];
    __shared__ float Bs[16][68];

    const int tid = threadIdx.x;
    const int tx  = tid & 15;
    const int ty  = tid >> 4;
    const int mBase = blockIdx.y * 64;
    const int nBase = blockIdx.x * 64;

    const int lr = tid >> 2;
    const int lk = (tid & 3) << 2;
    const int wr = tid >> 4;
    const int wn = (tid & 15) << 2;

    float c[4][4] = {};

    for (int k0 = 0; k0 < 256; k0 += 16) {
        float4 a = *(const float4*)&X[(mBase + lr) * 256 + k0 + lk];
        As[lk + 0][lr] = a.x; As[lk + 1][lr] = a.y;
        As[lk + 2][lr] = a.z; As[lk + 3][lr] = a.w;
        float4 bvec = *(const float4*)&W[(k0 + wr) * 256 + nBase + wn];
        *(float4*)&Bs[wr][wn] = bvec;
        __syncthreads();

        #pragma unroll
        for (int k = 0; k < 16; k++) {
            float4 av = *(float4*)&As[k][ty * 4];
            float4 bv = *(float4*)&Bs[k][tx * 4];
            float ar[4] = {av.x, av.y, av.z, av.w};
            float br[4] = {bv.x, bv.y, bv.z, bv.w};
            #pragma unroll
            for (int i = 0; i < 4; i++)
                #pragma unroll
                for (int j = 0; j < 4; j++)
                    c[i][j] += ar[i] * br[j];
        }
        __syncthreads();
    }

    float4 bb = *(const float4*)&bias[nBase + tx * 4];
    float bl[4] = {bb.x, bb.y, bb.z, bb.w};
    #pragma unroll
    for (int i = 0; i < 4; i++) {
        float4 o;
        o.x = c[i][0] + bl[0];
        o.y = c[i][1] + bl[1];
        o.z = c[i][2] + bl[2];
        o.w = c[i][3] + bl[3];
        *(float4*)&out[(mBase + ty * 4 + i) * 256 + nBase + tx * 4] = o;
    }
}

// ---------------------------------------------------------------------------
// Flash attention via 3xTF32 mma.sync (m16n8k8).
// CTA = 128 threads (4 warps). BQ=64 (warp owns 16 rows). BK=64. D=32.
// Grid: (L/64, B*NH) = (32, 16).
//
// smem (floats, dynamic):
//   Qs   [64][36]           offset 0      (raw Q tile)
//   Khi  [64][36]           2304          (tf32-hi of K, layout [key][d])
//   Klo  [64][36]           4608
//   Vhi  [64][40]           6912          (layout [key][d])
//   Vlo  [64][40]           9472
//   P    per-warp 2304 @    12032 + 2304*warp  (Phi[16][72], Plo[16][72])
// total 21248 floats = 84992 B -> 2 CTAs/SM.
// ---------------------------------------------------------------------------
#define QS_PITCH 36
#define K_PITCH 36
#define V_PITCH 40
#define P_PITCH 72
#define SMEM_FLOATS 21248

__global__ __launch_bounds__(128) void attn_tf32_kernel()
{
    extern __shared__ float sm[];
    float* Qs  = sm;
    float* Khi = sm + 2304;
    float* Klo = sm + 4608;
    float* Vhi = sm + 6912;
    float* Vlo = sm + 9472;

    const int tid  = threadIdx.x;
    const int warp = tid >> 5;
    const int lane = tid & 31;
    const int g    = lane >> 2;     // groupID 0..7
    const int t4   = lane & 3;      // thread-in-group

    float* Phi = sm + 12032 + warp * 2304;
    float* Plo = Phi + 1152;

    const int bh = blockIdx.y;
    const int b  = bh >> 3;
    const int h  = bh & 7;
    const int qBase = blockIdx.x * 64;
    const int q0 = warp * 16;
    const float scale = 0.17677669529663687f;   // 32^-0.5

    // ---- load Q tile (raw) ----
    for (int idx = tid; idx < 512; idx += 128) {
        int q = idx >> 3, dg = (idx & 7) << 2;
        *(float4*)&Qs[q * QS_PITCH + dg] =
            *(const float4*)&g_Q[((qBase + q) * B_SZ + b) * E_DIM + h * HD + dg];
    }
    __syncthreads();

    // ---- per-warp Q fragments, pre-scaled + split ----
    uint32_t qh[4][4], ql[4][4];
    {
        int r0 = (q0 + g) * QS_PITCH;
        int r1 = (q0 + g + 8) * QS_PITCH;
        #pragma unroll
        for (int kk = 0; kk < 4; kk++) {
            int c = kk * 8 + t4;
            float hi, lo;
            split2(Qs[r0 + c] * scale, hi, lo);
            qh[kk][0] = __float_as_uint(hi); ql[kk][0] = __float_as_uint(lo);
            split2(Qs[r1 + c] * scale, hi, lo);
            qh[kk][1] = __float_as_uint(hi); ql[kk][1] = __float_as_uint(lo);
            split2(Qs[r0 + c + 4] * scale, hi, lo);
            qh[kk][2] = __float_as_uint(hi); ql[kk][2] = __float_as_uint(lo);
            split2(Qs[r1 + c + 4] * scale, hi, lo);
            qh[kk][3] = __float_as_uint(hi); ql[kk][3] = __float_as_uint(lo);
        }
    }

    float m0 = -1e30f, m1 = -1e30f, l0 = 0.f, l1 = 0.f;
    float o[4][4];
    #pragma unroll
    for (int n = 0; n < 4; n++)
        o[n][0] = o[n][1] = o[n][2] = o[n][3] = 0.f;

    for (int kt = 0; kt < L_SEQ / 64; kt++) {
        __syncthreads();   // previous tile's consumers done
        // ---- load + split K,V tile ----
        for (int idx = tid; idx < 512; idx += 128) {
            int key = idx >> 3, dg = (idx & 7) << 2;
            int grow = ((kt * 64 + key) * B_SZ + b) * E_DIM + h * HD + dg;
            float4 kv = *(const float4*)&g_K[grow];
            float4 vv = *(const float4*)&g_V[grow];
            float4 khf, klf, vhf, vlf;
            split2(kv.x, khf.x, klf.x); split2(kv.y, khf.y, klf.y);
            split2(kv.z, khf.z, klf.z); split2(kv.w, khf.w, klf.w);
            split2(vv.x, vhf.x, vlf.x); split2(vv.y, vhf.y, vlf.y);
            split2(vv.z, vhf.z, vlf.z); split2(vv.w, vhf.w, vlf.w);
            *(float4*)&Khi[key * K_PITCH + dg] = khf;
            *(float4*)&Klo[key * K_PITCH + dg] = klf;
            *(float4*)&Vhi[key * V_PITCH + dg] = vhf;
            *(float4*)&Vlo[key * V_PITCH + dg] = vlf;
        }
        __syncthreads();

        // ---- S = Q K^T (3xTF32) ----
        float s[8][4];
        #pragma unroll
        for (int j = 0; j < 8; j++)
            s[j][0] = s[j][1] = s[j][2] = s[j][3] = 0.f;
        #pragma unroll
        for (int j = 0; j < 8; j++) {
            int krow = (j * 8 + g) * K_PITCH;
            #pragma unroll
            for (int kk = 0; kk < 4; kk++) {
                int c = kk * 8 + t4;
                uint32_t kb0 = __float_as_uint(Khi[krow + c]);
                uint32_t kb1 = __float_as_uint(Khi[krow + c + 4]);
                uint32_t lb0 = __float_as_uint(Klo[krow + c]);
                uint32_t lb1 = __float_as_uint(Klo[krow + c + 4]);
                mma8(s[j], qh[kk], kb0, kb1);
                mma8(s[j], ql[kk], kb0, kb1);
                mma8(s[j], qh[kk], lb0, lb1);
            }
        }

        // ---- online softmax ----
        float mx0 = -1e30f, mx1 = -1e30f;
        #pragma unroll
        for (int j = 0; j < 8; j++) {
            mx0 = fmaxf(mx0, fmaxf(s[j][0], s[j][1]));
            mx1 = fmaxf(mx1, fmaxf(s[j][2], s[j][3]));
        }
        mx0 = fmaxf(mx0, __shfl_xor_sync(0xffffffffu, mx0, 1));
        mx0 = fmaxf(mx0, __shfl_xor_sync(0xffffffffu, mx0, 2));
        mx1 = fmaxf(mx1, __shfl_xor_sync(0xffffffffu, mx1, 1));
        mx1 = fmaxf(mx1, __shfl_xor_sync(0xffffffffu, mx1, 2));
        float mn0 = fmaxf(m0, mx0), mn1 = fmaxf(m1, mx1);
        float al0 = __expf(m0 - mn0), al1 = __expf(m1 - mn1);
        float sum0 = 0.f, sum1 = 0.f;
        #pragma unroll
        for (int j = 0; j < 8; j++) {
            s[j][0] = __expf(s[j][0] - mn0);
            s[j][1] = __expf(s[j][1] - mn0);
            sum0 += s[j][0] + s[j][1];
            s[j][2] = __expf(s[j][2] - mn1);
            s[j][3] = __expf(s[j][3] - mn1);
            sum1 += s[j][2] + s[j][3];
        }
        sum0 += __shfl_xor_sync(0xffffffffu, sum0, 1);
        sum0 += __shfl_xor_sync(0xffffffffu, sum0, 2);
        sum1 += __shfl_xor_sync(0xffffffffu, sum1, 1);
        sum1 += __shfl_xor_sync(0xffffffffu, sum1, 2);
        l0 = l0 * al0 + sum0; m0 = mn0;
        l1 = l1 * al1 + sum1; m1 = mn1;
        #pragma unroll
        for (int n = 0; n < 4; n++) {
            o[n][0] *= al0; o[n][1] *= al0;
            o[n][2] *= al1; o[n][3] *= al1;
        }

        // ---- P -> smem (hi/lo split) ----
        #pragma unroll
        for (int j = 0; j < 8; j++) {
            int c = j * 8 + 2 * t4;
            float h0, e0, h1, e1, h2, e2, h3, e3;
            split2(s[j][0], h0, e0); split2(s[j][1], h1, e1);
            split2(s[j][2], h2, e2); split2(s[j][3], h3, e3);
            *(float2*)&Phi[g * P_PITCH + c]       = make_float2(h0, h1);
            *(float2*)&Plo[g * P_PITCH + c]       = make_float2(e0, e1);
            *(float2*)&Phi[(g + 8) * P_PITCH + c] = make_float2(h2, h3);
            *(float2*)&Plo[(g + 8) * P_PITCH + c] = make_float2(e2, e3);
        }
        __syncwarp();

        // ---- O += P V (3xTF32) ----
        #pragma unroll
        for (int ks = 0; ks < 8; ks++) {
            uint32_t pa[4], pl[4];
            int pc = ks * 8 + t4;
            pa[0] = __float_as_uint(Phi[g * P_PITCH + pc]);
            pa[1] = __float_as_uint(Phi[(g + 8) * P_PITCH + pc]);
            pa[2] = __float_as_uint(Phi[g * P_PITCH + pc + 4]);
            pa[3] = __float_as_uint(Phi[(g + 8) * P_PITCH + pc + 4]);
            pl[0] = __float_as_uint(Plo[g * P_PITCH + pc]);
            pl[1] = __float_as_uint(Plo[(g + 8) * P_PITCH + pc]);
            pl[2] = __float_as_uint(Plo[g * P_PITCH + pc + 4]);
            pl[3] = __float_as_uint(Plo[(g + 8) * P_PITCH + pc + 4]);
            int vr0 = (ks * 8 + t4) * V_PITCH;
            int vr1 = (ks * 8 + t4 + 4) * V_PITCH;
            #pragma unroll
            for (int n = 0; n < 4; n++) {
                int d0 = n * 8 + g;
                uint32_t vb0 = __float_as_uint(Vhi[vr0 + d0]);
                uint32_t vb1 = __float_as_uint(Vhi[vr1 + d0]);
                uint32_t wb0 = __float_as_uint(Vlo[vr0 + d0]);
                uint32_t wb1 = __float_as_uint(Vlo[vr1 + d0]);
                mma8(o[n], pa, vb0, vb1);
                mma8(o[n], pl, vb0, vb1);
                mma8(o[n], pa, wb0, wb1);
            }
        }
    }

    // ---- epilogue ----
    float inv0 = 1.0f / l0, inv1 = 1.0f / l1;
    int qr0 = qBase + q0 + g;
    int qr1 = qr0 + 8;
    #pragma unroll
    for (int n = 0; n < 4; n++) {
        int col = h * HD + n * 8 + 2 * t4;
        *(float2*)&g_O[(qr0 * B_SZ + b) * E_DIM + col] =
            make_float2(o[n][0] * inv0, o[n][1] * inv0);
        *(float2*)&g_O[(qr1 * B_SZ + b) * E_DIM + col] =
            make_float2(o[n][2] * inv1, o[n][3] * inv1);
    }
}

// ---------------------------------------------------------------------------
extern "C" void kernel_launch(void* const* d_in, const int* in_sizes, int n_in,
                              void* d_out, int out_size)
{
    const float* query = (const float*)d_in[0];
    const float* key_  = (const float*)d_in[1];
    const float* value = (const float*)d_in[2];
    const float* Wq = (const float*)d_in[3];
    const float* bq = (const float*)d_in[4];
    const float* Wk = (const float*)d_in[5];
    const float* bk = (const float*)d_in[6];
    const float* Wv = (const float*)d_in[7];
    const float* bv = (const float*)d_in[8];
    const float* Wp = (const float*)d_in[9];
    const float* bp = (const float*)d_in[10];
    float* out = (float*)d_out;

    float *qbuf, *kbuf, *vbuf, *obuf;
    cudaGetSymbolAddress((void**)&qbuf, g_Q);
    cudaGetSymbolAddress((void**)&kbuf, g_K);
    cudaGetSymbolAddress((void**)&vbuf, g_V);
    cudaGetSymbolAddress((void**)&obuf, g_O);

    cudaFuncSetAttribute(attn_tf32_kernel,
                         cudaFuncAttributeMaxDynamicSharedMemorySize,
                         SMEM_FLOATS * 4);

    dim3 gg(E_DIM / 64, M_ROWS / 64);
    gemm_bias_kernel<<<gg, 256>>>(query, Wq, bq, qbuf);
    gemm_bias_kernel<<<gg, 256>>>(key_,  Wk, bk, kbuf);
    gemm_bias_kernel<<<gg, 256>>>(value, Wv, bv, vbuf);
    attn_tf32_kernel<<<dim3(L_SEQ / 64, B_SZ * NH), 128, SMEM_FLOATS * 4>>>();
    gemm_bias_kernel<<<gg, 256>>>(obuf, Wp, bp, out);
}

// round 3
// speedup vs baseline: 1.6027x; 1.3060x over previous
#include <cuda_runtime.h>
#include <math.h>
#include <stdint.h>

#define L_SEQ 2048
#define B_SZ 2
#define E_DIM 256
#define NH 8
#define HD 32
#define M_ROWS (L_SEQ * B_SZ)   // 4096

// Scratch (allocation-free rule: __device__ globals)
static __device__ float g_Q[M_ROWS * E_DIM];
static __device__ float g_K[M_ROWS * E_DIM];
static __device__ float g_V[M_ROWS * E_DIM];
static __device__ float g_O[M_ROWS * E_DIM];

// ---------------------------------------------------------------------------
// helpers: tf32 convert / hi-lo split / mma
// ---------------------------------------------------------------------------
__device__ __forceinline__ uint32_t f2tf(float x) {
    uint32_t r; asm("cvt.rna.tf32.f32 %0, %1;" : "=r"(r) : "f"(x)); return r;
}
__device__ __forceinline__ void split2(float x, float& hi, float& lo) {
    uint32_t h = f2tf(x);
    hi = __uint_as_float(h);
    lo = __uint_as_float(f2tf(x - hi));
}
__device__ __forceinline__ void mma8(float c[4], const uint32_t a[4],
                                     uint32_t b0, uint32_t b1) {
    asm volatile(
        "mma.sync.aligned.m16n8k8.row.col.f32.tf32.tf32.f32 "
        "{%0,%1,%2,%3}, {%4,%5,%6,%7}, {%8,%9}, {%0,%1,%2,%3};"
        : "+f"(c[0]), "+f"(c[1]), "+f"(c[2]), "+f"(c[3])
        : "r"(a[0]), "r"(a[1]), "r"(a[2]), "r"(a[3]), "r"(b0), "r"(b1));
}

// ---------------------------------------------------------------------------
// GEMM: out[M,N] = X[M,256] @ W[256,N] + bias[N]  (fp32 SIMT, unchanged)
// ---------------------------------------------------------------------------
__global__ __launch_bounds__(256) void gemm_bias_kernel(
    const float* __restrict__ X, const float* __restrict__ W,
    const float* __restrict__ bias, float* __restrict__ out)
{
    __shared__ float As[16][68];
    __shared__ float Bs[16][68];

    const int tid = threadIdx.x;
    const int tx  = tid & 15;
    const int ty  = tid >> 4;
    const int mBase = blockIdx.y * 64;
    const int nBase = blockIdx.x * 64;

    const int lr = tid >> 2;
    const int lk = (tid & 3) << 2;
    const int wr = tid >> 4;
    const int wn = (tid & 15) << 2;

    float c[4][4] = {};

    for (int k0 = 0; k0 < 256; k0 += 16) {
        float4 a = *(const float4*)&X[(mBase + lr) * 256 + k0 + lk];
        As[lk + 0][lr] = a.x; As[lk + 1][lr] = a.y;
        As[lk + 2][lr] = a.z; As[lk + 3][lr] = a.w;
        float4 bvec = *(const float4*)&W[(k0 + wr) * 256 + nBase + wn];
        *(float4*)&Bs[wr][wn] = bvec;
        __syncthreads();

        #pragma unroll
        for (int k = 0; k < 16; k++) {
            float4 av = *(float4*)&As[k][ty * 4];
            float4 bv = *(float4*)&Bs[k][tx * 4];
            float ar[4] = {av.x, av.y, av.z, av.w};
            float br[4] = {bv.x, bv.y, bv.z, bv.w};
            #pragma unroll
            for (int i = 0; i < 4; i++)
                #pragma unroll
                for (int j = 0; j < 4; j++)
                    c[i][j] += ar[i] * br[j];
        }
        __syncthreads();
    }

    float4 bb = *(const float4*)&bias[nBase + tx * 4];
    float bl[4] = {bb.x, bb.y, bb.z, bb.w};
    #pragma unroll
    for (int i = 0; i < 4; i++) {
        float4 o;
        o.x = c[i][0] + bl[0];
        o.y = c[i][1] + bl[1];
        o.z = c[i][2] + bl[2];
        o.w = c[i][3] + bl[3];
        *(float4*)&out[(mBase + ty * 4 + i) * 256 + nBase + tx * 4] = o;
    }
}

// ---------------------------------------------------------------------------
// Flash attention via TF32 mma.sync (m16n8k8), occupancy-optimized.
// CTA = 128 threads (4 warps), BQ=64 (warp owns 16 rows), BK=64, D=32.
// Grid: (L/64, B*NH) = (32, 16).
// QK^T: 3-term tf32 split (full fp32 accuracy). PV: P rounded to tf32 (rna),
// V split hi/lo -> 2 mmas (error ~2.4e-4, within 1e-3 budget).
// P C-fragment -> A-fragment conversion done with intra-quad shuffles
// (no smem round-trip). smem = 38 KB -> 4 CTAs/SM (16 warps).
// ---------------------------------------------------------------------------
#define K_PITCH 36
#define V_PITCH 40

__global__ __launch_bounds__(128, 4) void attn_tf32_kernel()
{
    __shared__ float Khi[64 * K_PITCH];
    __shared__ float Klo[64 * K_PITCH];
    __shared__ float Vhi[64 * V_PITCH];
    __shared__ float Vlo[64 * V_PITCH];

    const int tid  = threadIdx.x;
    const int warp = tid >> 5;
    const int lane = tid & 31;
    const int g    = lane >> 2;     // groupID 0..7
    const int t4   = lane & 3;      // thread-in-group

    const int bh = blockIdx.y;
    const int b  = bh >> 3;
    const int h  = bh & 7;
    const int qBase = blockIdx.x * 64;
    const int q0 = warp * 16;
    const float scale = 0.17677669529663687f;   // 32^-0.5

    // ---- Q fragments straight from gmem (one-time), pre-scaled + split ----
    uint32_t qh[4][4], ql[4][4];
    {
        const float* qrow0 = &g_Q[((qBase + q0 + g) * B_SZ + b) * E_DIM + h * HD];
        const float* qrow1 = &g_Q[((qBase + q0 + g + 8) * B_SZ + b) * E_DIM + h * HD];
        #pragma unroll
        for (int kk = 0; kk < 4; kk++) {
            int c = kk * 8 + t4;
            float hi, lo;
            split2(qrow0[c] * scale, hi, lo);
            qh[kk][0] = __float_as_uint(hi); ql[kk][0] = __float_as_uint(lo);
            split2(qrow1[c] * scale, hi, lo);
            qh[kk][1] = __float_as_uint(hi); ql[kk][1] = __float_as_uint(lo);
            split2(qrow0[c + 4] * scale, hi, lo);
            qh[kk][2] = __float_as_uint(hi); ql[kk][2] = __float_as_uint(lo);
            split2(qrow1[c + 4] * scale, hi, lo);
            qh[kk][3] = __float_as_uint(hi); ql[kk][3] = __float_as_uint(lo);
        }
    }

    float m0 = -1e30f, m1 = -1e30f, l0 = 0.f, l1 = 0.f;
    float o[4][4];
    #pragma unroll
    for (int n = 0; n < 4; n++)
        o[n][0] = o[n][1] = o[n][2] = o[n][3] = 0.f;

    for (int kt = 0; kt < L_SEQ / 64; kt++) {
        if (kt) __syncthreads();   // previous tile's consumers done
        // ---- load + split K,V tile ----
        for (int idx = tid; idx < 512; idx += 128) {
            int key = idx >> 3, dg = (idx & 7) << 2;
            int grow = ((kt * 64 + key) * B_SZ + b) * E_DIM + h * HD + dg;
            float4 kv = *(const float4*)&g_K[grow];
            float4 vv = *(const float4*)&g_V[grow];
            float4 khf, klf, vhf, vlf;
            split2(kv.x, khf.x, klf.x); split2(kv.y, khf.y, klf.y);
            split2(kv.z, khf.z, klf.z); split2(kv.w, khf.w, klf.w);
            split2(vv.x, vhf.x, vlf.x); split2(vv.y, vhf.y, vlf.y);
            split2(vv.z, vhf.z, vlf.z); split2(vv.w, vhf.w, vlf.w);
            *(float4*)&Khi[key * K_PITCH + dg] = khf;
            *(float4*)&Klo[key * K_PITCH + dg] = klf;
            *(float4*)&Vhi[key * V_PITCH + dg] = vhf;
            *(float4*)&Vlo[key * V_PITCH + dg] = vlf;
        }
        __syncthreads();

        // ---- S = Q K^T (3xTF32) ----
        float s[8][4];
        #pragma unroll
        for (int j = 0; j < 8; j++)
            s[j][0] = s[j][1] = s[j][2] = s[j][3] = 0.f;
        #pragma unroll
        for (int j = 0; j < 8; j++) {
            int krow = (j * 8 + g) * K_PITCH;
            #pragma unroll
            for (int kk = 0; kk < 4; kk++) {
                int c = kk * 8 + t4;
                uint32_t kb0 = __float_as_uint(Khi[krow + c]);
                uint32_t kb1 = __float_as_uint(Khi[krow + c + 4]);
                uint32_t lb0 = __float_as_uint(Klo[krow + c]);
                uint32_t lb1 = __float_as_uint(Klo[krow + c + 4]);
                mma8(s[j], qh[kk], kb0, kb1);
                mma8(s[j], ql[kk], kb0, kb1);
                mma8(s[j], qh[kk], lb0, lb1);
            }
        }

        // ---- online softmax ----
        float mx0 = -1e30f, mx1 = -1e30f;
        #pragma unroll
        for (int j = 0; j < 8; j++) {
            mx0 = fmaxf(mx0, fmaxf(s[j][0], s[j][1]));
            mx1 = fmaxf(mx1, fmaxf(s[j][2], s[j][3]));
        }
        mx0 = fmaxf(mx0, __shfl_xor_sync(0xffffffffu, mx0, 1));
        mx0 = fmaxf(mx0, __shfl_xor_sync(0xffffffffu, mx0, 2));
        mx1 = fmaxf(mx1, __shfl_xor_sync(0xffffffffu, mx1, 1));
        mx1 = fmaxf(mx1, __shfl_xor_sync(0xffffffffu, mx1, 2));
        float mn0 = fmaxf(m0, mx0), mn1 = fmaxf(m1, mx1);
        float al0 = __expf(m0 - mn0), al1 = __expf(m1 - mn1);
        float sum0 = 0.f, sum1 = 0.f;
        #pragma unroll
        for (int j = 0; j < 8; j++) {
            s[j][0] = __expf(s[j][0] - mn0);
            s[j][1] = __expf(s[j][1] - mn0);
            sum0 += s[j][0] + s[j][1];
            s[j][2] = __expf(s[j][2] - mn1);
            s[j][3] = __expf(s[j][3] - mn1);
            sum1 += s[j][2] + s[j][3];
        }
        sum0 += __shfl_xor_sync(0xffffffffu, sum0, 1);
        sum0 += __shfl_xor_sync(0xffffffffu, sum0, 2);
        sum1 += __shfl_xor_sync(0xffffffffu, sum1, 1);
        sum1 += __shfl_xor_sync(0xffffffffu, sum1, 2);
        l0 = l0 * al0 + sum0; m0 = mn0;
        l1 = l1 * al1 + sum1; m1 = mn1;
        #pragma unroll
        for (int n = 0; n < 4; n++) {
            o[n][0] *= al0; o[n][1] *= al0;
            o[n][2] *= al1; o[n][3] *= al1;
        }

        // ---- O += P V : C-frag -> A-frag via intra-quad shuffles ----
        // P(grp_row, c) with c = 2*src_t4 + slot lives in lane (g, c>>1),
        // register s[ks][slot] (rows g) / s[ks][2+slot] (rows g+8).
        #pragma unroll
        for (int ks = 0; ks < 8; ks++) {
            const int hsrc  = (lane & 28) + (t4 >> 1);  // g*4 + t4/2
            const int hsrc2 = hsrc + 2;
            const bool odd = (t4 & 1);
            float b0 = __shfl_sync(0xffffffffu, s[ks][0], hsrc);
            float b1 = __shfl_sync(0xffffffffu, s[ks][1], hsrc);
            float c0 = __shfl_sync(0xffffffffu, s[ks][2], hsrc);
            float c1 = __shfl_sync(0xffffffffu, s[ks][3], hsrc);
            float d0 = __shfl_sync(0xffffffffu, s[ks][0], hsrc2);
            float d1 = __shfl_sync(0xffffffffu, s[ks][1], hsrc2);
            float e0 = __shfl_sync(0xffffffffu, s[ks][2], hsrc2);
            float e1 = __shfl_sync(0xffffffffu, s[ks][3], hsrc2);
            uint32_t pa[4];
            pa[0] = f2tf(odd ? b1 : b0);
            pa[1] = f2tf(odd ? c1 : c0);
            pa[2] = f2tf(odd ? d1 : d0);
            pa[3] = f2tf(odd ? e1 : e0);

            int vr0 = (ks * 8 + t4) * V_PITCH;
            int vr1 = (ks * 8 + t4 + 4) * V_PITCH;
            #pragma unroll
            for (int n = 0; n < 4; n++) {
                int d0i = n * 8 + g;
                uint32_t vb0 = __float_as_uint(Vhi[vr0 + d0i]);
                uint32_t vb1 = __float_as_uint(Vhi[vr1 + d0i]);
                uint32_t wb0 = __float_as_uint(Vlo[vr0 + d0i]);
                uint32_t wb1 = __float_as_uint(Vlo[vr1 + d0i]);
                mma8(o[n], pa, vb0, vb1);
                mma8(o[n], pa, wb0, wb1);
            }
        }
    }

    // ---- epilogue ----
    float inv0 = 1.0f / l0, inv1 = 1.0f / l1;
    int qr0 = qBase + q0 + g;
    int qr1 = qr0 + 8;
    #pragma unroll
    for (int n = 0; n < 4; n++) {
        int col = h * HD + n * 8 + 2 * t4;
        *(float2*)&g_O[(qr0 * B_SZ + b) * E_DIM + col] =
            make_float2(o[n][0] * inv0, o[n][1] * inv0);
        *(float2*)&g_O[(qr1 * B_SZ + b) * E_DIM + col] =
            make_float2(o[n][2] * inv1, o[n][3] * inv1);
    }
}

// ---------------------------------------------------------------------------
extern "C" void kernel_launch(void* const* d_in, const int* in_sizes, int n_in,
                              void* d_out, int out_size)
{
    const float* query = (const float*)d_in[0];
    const float* key_  = (const float*)d_in[1];
    const float* value = (const float*)d_in[2];
    const float* Wq = (const float*)d_in[3];
    const float* bq = (const float*)d_in[4];
    const float* Wk = (const float*)d_in[5];
    const float* bk = (const float*)d_in[6];
    const float* Wv = (const float*)d_in[7];
    const float* bv = (const float*)d_in[8];
    const float* Wp = (const float*)d_in[9];
    const float* bp = (const float*)d_in[10];
    float* out = (float*)d_out;

    float *qbuf, *kbuf, *vbuf, *obuf;
    cudaGetSymbolAddress((void**)&qbuf, g_Q);
    cudaGetSymbolAddress((void**)&kbuf, g_K);
    cudaGetSymbolAddress((void**)&vbuf, g_V);
    cudaGetSymbolAddress((void**)&obuf, g_O);

    dim3 gg(E_DIM / 64, M_ROWS / 64);
    gemm_bias_kernel<<<gg, 256>>>(query, Wq, bq, qbuf);
    gemm_bias_kernel<<<gg, 256>>>(key_,  Wk, bk, kbuf);
    gemm_bias_kernel<<<gg, 256>>>(value, Wv, bv, vbuf);
    attn_tf32_kernel<<<dim3(L_SEQ / 64, B_SZ * NH), 128>>>();
    gemm_bias_kernel<<<gg, 256>>>(obuf, Wp, bp, out);
}